// round 13
// baseline (speedup 1.0000x reference)
#include <cuda_runtime.h>

// inputs: [128, 65536, 3] f32 interleaved (x,y,z)
// output: [128, 65536, 2] f32: (-(clip(x,-1,1)+1)*90, atan2(z,y)*180/pi)
//
// psi = acos(y/sqrt(y^2+z^2)) with sign of z  ==  atan2(z, y)
//
// Coalesce the 48B-strided input through smem: each thread LOADS a
// consecutive float4 triplet (warp covers 512B per LDG -> 4 lines, not 12),
// parks in smem, syncs once, then READS its own 3 float4s at 48B stride
// from smem (conflict-free in 8-lane phases) and computes. Stores direct.

#define TPB 256
#define F4_PER_BLOCK (TPB * 3)   // 768 float4s = 12 KB

static __device__ __forceinline__ float fast_atan2_deg(float z, float y) {
    // atan2(z,y) * (180/pi), minimax atan poly on [0,1], max err ~1e-5 rad
    float ay = fabsf(y), az = fabsf(z);
    float mn = fminf(ay, az), mx = fmaxf(ay, az);
    float a = __fdividef(mn, mx);
    float s = a * a;
    float r = fmaf(fmaf(fmaf(fmaf(0.0208351f, s, -0.0851330f),
                             s, 0.1801410f),
                        s, -0.3302995f),
                   s, 0.9998660f) * a;
    if (az > ay) r = 1.5707963267948966f - r;
    if (y < 0.0f) r = 3.14159265358979323f - r;
    r = (z < 0.0f) ? -r : r;
    return r * 57.295779513082323f;
}

static __device__ __forceinline__ void point_op(float x, float y, float z,
                                                float& o0, float& o1) {
    float cx = fminf(fmaxf(x, -1.0f), 1.0f);
    o0 = fmaf(cx, -90.0f, -90.0f);   // -(cx+1)*90
    o1 = fast_atan2_deg(z, y);
}

__global__ void __launch_bounds__(TPB) cil_kernel(const float4* __restrict__ in4,
                                                  float4* __restrict__ out4) {
    __shared__ float4 buf[F4_PER_BLOCK];
    int tid = threadIdx.x;
    size_t base = (size_t)blockIdx.x * F4_PER_BLOCK;

    // Coalesced loads: warp spans 512 contiguous bytes per LDG.128 (4 lines)
    float4 l0 = in4[base + tid + 0 * TPB];
    float4 l1 = in4[base + tid + 1 * TPB];
    float4 l2 = in4[base + tid + 2 * TPB];
    buf[tid + 0 * TPB] = l0;
    buf[tid + 1 * TPB] = l1;
    buf[tid + 2 * TPB] = l2;

    __syncthreads();

    // Strided smem reads: 48B lane stride, conflict-free per 8-lane phase
    float4 a = buf[3 * tid + 0];  // x0 y0 z0 x1
    float4 b = buf[3 * tid + 1];  // y1 z1 x2 y2
    float4 c = buf[3 * tid + 2];  // z2 x3 y3 z3

    float4 o0, o1;
    point_op(a.x, a.y, a.z, o0.x, o0.y);  // p0
    point_op(a.w, b.x, b.y, o0.z, o0.w);  // p1
    point_op(b.z, b.w, c.x, o1.x, o1.y);  // p2
    point_op(c.y, c.z, c.w, o1.z, o1.w);  // p3

    size_t t = (size_t)blockIdx.x * TPB + tid;
    out4[2 * t + 0] = o0;
    out4[2 * t + 1] = o1;
}

extern "C" void kernel_launch(void* const* d_in, const int* in_sizes, int n_in,
                              void* d_out, int out_size) {
    const float4* in4 = (const float4*)d_in[0];
    float4* out4 = (float4*)d_out;

    int n_points = in_sizes[0] / 3;      // 8,388,608
    int n_quads = n_points / 4;          // 2,097,152
    int blocks = n_quads / TPB;          // 8192 (exact)

    cil_kernel<<<blocks, TPB>>>(in4, out4);
}